// round 3
// baseline (speedup 1.0000x reference)
#include <cuda_runtime.h>
#include <cstdint>

#define NN 16384
#define NF 64
#define NC 16

// Scratch (no allocations allowed)
__device__ float    g_s  [NN * NF];
__device__ float    g_h1 [NN * NF];
__device__ float    g_h2 [NN * NF];
__device__ uint16_t g_bth[NF * NN];   // B^T hi bf16, [64][16384]
__device__ uint16_t g_btl[NF * NN];   // B^T lo bf16

// ---------------------------------------------------------------------------
// helpers
// ---------------------------------------------------------------------------
__device__ __forceinline__ uint32_t smem_u32(const void* p) {
    uint32_t a;
    asm("{ .reg .u64 t; cvta.to.shared.u64 t, %1; cvt.u32.u64 %0, t; }" : "=r"(a) : "l"(p));
    return a;
}
// pack bf16(lo), bf16(hi) -> b32 (lo in low half)
__device__ __forceinline__ uint32_t cvt2(float hi, float lo) {
    uint32_t r;
    asm("cvt.rn.bf16x2.f32 %0, %1, %2;" : "=r"(r) : "f"(hi), "f"(lo));
    return r;
}
__device__ __forceinline__ float lo_f(uint32_t p) { return __uint_as_float(p << 16); }
__device__ __forceinline__ float hi_f(uint32_t p) { return __uint_as_float(p & 0xffff0000u); }

__device__ __forceinline__ void ldsm4(uint32_t* r, uint32_t addr) {
    asm volatile("ldmatrix.sync.aligned.m8n8.x4.shared.b16 {%0,%1,%2,%3}, [%4];"
                 : "=r"(r[0]), "=r"(r[1]), "=r"(r[2]), "=r"(r[3]) : "r"(addr));
}
__device__ __forceinline__ void mma_bf(float* c, const uint32_t* a, const uint32_t* b) {
    asm volatile(
        "mma.sync.aligned.m16n8k16.row.col.f32.bf16.bf16.f32 "
        "{%0,%1,%2,%3}, {%4,%5,%6,%7}, {%8,%9}, {%0,%1,%2,%3};"
        : "+f"(c[0]), "+f"(c[1]), "+f"(c[2]), "+f"(c[3])
        : "r"(a[0]), "r"(a[1]), "r"(a[2]), "r"(a[3]), "r"(b[0]), "r"(b[1]));
}

// split v into hi/lo bf16 pairs for 8 consecutive values -> two uint4
__device__ __forceinline__ void split8(const float* v, uint4& h, uint4& l) {
    uint32_t h01 = cvt2(v[1], v[0]);
    uint32_t h23 = cvt2(v[3], v[2]);
    uint32_t h45 = cvt2(v[5], v[4]);
    uint32_t h67 = cvt2(v[7], v[6]);
    l.x = cvt2(v[1] - hi_f(h01), v[0] - lo_f(h01));
    l.y = cvt2(v[3] - hi_f(h23), v[2] - lo_f(h23));
    l.z = cvt2(v[5] - hi_f(h45), v[4] - lo_f(h45));
    l.w = cvt2(v[7] - hi_f(h67), v[6] - lo_f(h67));
    h = make_uint4(h01, h23, h45, h67);
}

// ---------------------------------------------------------------------------
// GEMM: C[NN,64] = A[NN,NN](fp32) @ B (B given pre-split/transposed bf16)
// split-bf16 3-term. Block 128x64, BK=32, 256 thr (8 warps, warp tile 32x32).
// smem per stage: Ah,Al [128][32]bf16 (8KB each) + Bh,Bl [64][32]bf16 (4KB each)
// seg swizzle: 16B seg index ^= (row>>1)&3  (conflict-free STS.128 + ldmatrix)
// ---------------------------------------------------------------------------
#define BK   32
#define AST  8192           // bytes, one A array per stage (128 rows * 64B)
#define BST  4096           // one B array per stage (64 rows * 64B)
#define STG  (2*AST + 2*BST)  // 24576
#define GSM  (2*STG)          // 49152

__global__ __launch_bounds__(256, 1) void gemm_bf(const float* __restrict__ A,
                                                  const uint16_t* __restrict__ Bth,
                                                  const uint16_t* __restrict__ Btl,
                                                  float* __restrict__ C) {
    extern __shared__ char smc[];
    const uint32_t smu = smem_u32(smc);

    const int tid  = threadIdx.x;
    const int lane = tid & 31, wid = tid >> 5;
    const int wm = (wid & 3) * 32;      // warp row offset (0..96)
    const int wn = (wid >> 2) * 32;     // warp col offset (0 or 32)
    const int br = blockIdx.x * 128;

    // prefetch register sets (3-deep)
    float4 ra[3][2][2];
    uint4  rbh[3], rbl[3];

    auto ldg = [&](int set, int it) {
        const int kt = it * BK;
        #pragma unroll
        for (int jj = 0; jj < 2; jj++) {
            const int s = tid + jj * 256;
            const int row = s >> 2, seg = s & 3;
            const float* p = &A[(size_t)(br + row) * NN + kt + seg * 8];
            ra[set][jj][0] = *(const float4*)p;
            ra[set][jj][1] = *(const float4*)(p + 4);
        }
        const int nr = tid >> 2, seg = tid & 3;
        rbh[set] = *(const uint4*)&Bth[(size_t)nr * NN + kt + seg * 8];
        rbl[set] = *(const uint4*)&Btl[(size_t)nr * NN + kt + seg * 8];
    };
    auto sts = [&](int set, int stg) {
        char* base = smc + stg * STG;
        #pragma unroll
        for (int jj = 0; jj < 2; jj++) {
            const int s = tid + jj * 256;
            const int row = s >> 2, seg = s & 3;
            const int sp = seg ^ ((row >> 1) & 3);
            float v[8] = {ra[set][jj][0].x, ra[set][jj][0].y, ra[set][jj][0].z, ra[set][jj][0].w,
                          ra[set][jj][1].x, ra[set][jj][1].y, ra[set][jj][1].z, ra[set][jj][1].w};
            uint4 h, l;
            split8(v, h, l);
            const int off = row * 64 + sp * 16;
            *(uint4*)(base + off)       = h;
            *(uint4*)(base + AST + off) = l;
        }
        const int nr = tid >> 2, seg = tid & 3;
        const int sp = seg ^ ((nr >> 1) & 3);
        const int off = 2 * AST + nr * 64 + sp * 16;
        *(uint4*)(base + off)       = rbh[set];
        *(uint4*)(base + BST + off) = rbl[set];
    };

    float acc[2][4][4];
    #pragma unroll
    for (int i = 0; i < 2; i++)
        #pragma unroll
        for (int j = 0; j < 4; j++)
            #pragma unroll
            for (int r = 0; r < 4; r++) acc[i][j][r] = 0.f;

    const int NT = NN / BK;   // 512

    ldg(0, 0);
    sts(0, 0);
    ldg(1, 1);
    ldg(2, 2);
    __syncthreads();

    // frag address components (constant per thread)
    const int rA   = lane & 15;                       // A row within m16
    const int sA   = lane >> 4;                       // A k-half
    const int rB   = (lane & 7) + ((lane >> 4) << 3); // B n row within n16
    const int sB   = (lane >> 3) & 1;                 // B k-half

    for (int it = 0; it < NT; ++it) {
        const int stg = it & 1;
        if (it + 1 < NT) sts((it + 1) % 3, stg ^ 1);
        if (it + 3 < NT) ldg(it % 3, it + 3);

        const uint32_t base = smu + stg * STG;
        #pragma unroll
        for (int j = 0; j < 2; j++) {                 // two k16 steps
            uint32_t ah[2][4], al[2][4], bh[2][4], bl[2][4];
            #pragma unroll
            for (int t16 = 0; t16 < 2; t16++) {
                const int row = wm + t16 * 16 + rA;
                const int seg = (2 * j + sA) ^ ((row >> 1) & 3);
                const uint32_t ad = base + row * 64 + seg * 16;
                ldsm4(ah[t16], ad);
                ldsm4(al[t16], ad + AST);
            }
            #pragma unroll
            for (int h = 0; h < 2; h++) {
                const int n = wn + h * 16 + rB;
                const int seg = (2 * j + sB) ^ ((n >> 1) & 3);
                const uint32_t bd = base + 2 * AST + n * 64 + seg * 16;
                ldsm4(bh[h], bd);
                ldsm4(bl[h], bd + BST);
            }
            #pragma unroll
            for (int t16 = 0; t16 < 2; t16++)
                #pragma unroll
                for (int nt = 0; nt < 4; nt++) {
                    const uint32_t* ph = &bh[nt >> 1][(nt & 1) * 2];
                    const uint32_t* pl = &bl[nt >> 1][(nt & 1) * 2];
                    mma_bf(acc[t16][nt], ah[t16], ph);
                    mma_bf(acc[t16][nt], ah[t16], pl);
                    mma_bf(acc[t16][nt], al[t16], ph);
                }
        }
        __syncthreads();
    }

    const int g = lane >> 2, t = lane & 3;
    #pragma unroll
    for (int t16 = 0; t16 < 2; t16++)
        #pragma unroll
        for (int nt = 0; nt < 4; nt++) {
            const size_t r0 = br + wm + t16 * 16 + g;
            const int c0 = wn + nt * 8 + 2 * t;
            *(float2*)&C[r0 * NF + c0]       = make_float2(acc[t16][nt][0], acc[t16][nt][1]);
            *(float2*)&C[(r0 + 8) * NF + c0] = make_float2(acc[t16][nt][2], acc[t16][nt][3]);
        }
}

// ---------------------------------------------------------------------------
// Prep: src[NN][64] fp32 -> Bth, Btl [64][NN] bf16 (transpose + split)
// 64 src rows per block, 256 threads, grid 256.
// ---------------------------------------------------------------------------
__global__ __launch_bounds__(256) void bt2_kernel(const float* __restrict__ src,
                                                  uint16_t* __restrict__ bth,
                                                  uint16_t* __restrict__ btl) {
    __shared__ float ts[64 * 65];
    const int tid = threadIdx.x;
    const int r0  = blockIdx.x * 64;

    #pragma unroll
    for (int j = 0; j < 4; j++) {
        const int idx = tid + j * 256;
        const int r = idx >> 4, c = (idx & 15) * 4;
        float4 v = *(const float4*)&src[(size_t)(r0 + r) * NF + c];
        ts[r * 65 + c + 0] = v.x;
        ts[r * 65 + c + 1] = v.y;
        ts[r * 65 + c + 2] = v.z;
        ts[r * 65 + c + 3] = v.w;
    }
    __syncthreads();
    #pragma unroll
    for (int j = 0; j < 4; j++) {
        const int idx = tid + j * 256;
        const int n = idx >> 4, kq = (idx & 15) * 4;
        float v[4];
        #pragma unroll
        for (int i = 0; i < 4; i++) v[i] = ts[(kq + i) * 65 + n];
        uint32_t h01 = cvt2(v[1], v[0]);
        uint32_t h23 = cvt2(v[3], v[2]);
        uint32_t l01 = cvt2(v[1] - hi_f(h01), v[0] - lo_f(h01));
        uint32_t l23 = cvt2(v[3] - hi_f(h23), v[2] - lo_f(h23));
        *(uint2*)&bth[(size_t)n * NN + r0 + kq] = make_uint2(h01, h23);
        *(uint2*)&btl[(size_t)n * NN + r0 + kq] = make_uint2(l01, l23);
    }
}

// ---------------------------------------------------------------------------
// H = relu([X | S] @ W), W [128][64]. 64 nodes/block, 256 threads, 16 cols/thr.
// ---------------------------------------------------------------------------
#define LSMEM (128 * 64 * 4 + 2 * 64 * 68 * 4)
__global__ __launch_bounds__(256) void layer_kernel(const float* __restrict__ X,
                                                    const float* __restrict__ S,
                                                    const float* __restrict__ W,
                                                    float* __restrict__ H) {
    extern __shared__ float lsm[];
    float* Ws = lsm;                // [128][64]
    float* xs = Ws + 128 * 64;      // [64][68]
    float* ss = xs + 64 * 68;       // [64][68]
    const int tid  = threadIdx.x;
    const size_t nb = (size_t)blockIdx.x * 64;

    #pragma unroll
    for (int j = 0; j < 8; j++)
        *(float4*)&Ws[(tid + j * 256) * 4] = *(const float4*)&W[(tid + j * 256) * 4];
    #pragma unroll
    for (int j = 0; j < 4; j++) {
        const int idx = tid + j * 256;
        const int r = idx >> 4, c = (idx & 15) * 4;
        float4 xv = *(const float4*)&X[(nb + r) * NF + c];
        float4 sv = *(const float4*)&S[(nb + r) * NF + c];
        xs[r * 68 + c] = xv.x; xs[r * 68 + c + 1] = xv.y;
        xs[r * 68 + c + 2] = xv.z; xs[r * 68 + c + 3] = xv.w;
        ss[r * 68 + c] = sv.x; ss[r * 68 + c + 1] = sv.y;
        ss[r * 68 + c + 2] = sv.z; ss[r * 68 + c + 3] = sv.w;
    }
    __syncthreads();

    const int ni = tid >> 2, jb = (tid & 3) * 16;
    float acc[16];
    #pragma unroll
    for (int c = 0; c < 16; c++) acc[c] = 0.f;

    #pragma unroll 8
    for (int f = 0; f < 64; f++) {
        const float xv = xs[ni * 68 + f];
        const float sv = ss[ni * 68 + f];
        #pragma unroll
        for (int c4 = 0; c4 < 4; c4++) {
            float4 wx  = *(const float4*)&Ws[f * 64 + jb + c4 * 4];
            float4 wsv = *(const float4*)&Ws[(64 + f) * 64 + jb + c4 * 4];
            acc[c4 * 4 + 0] += xv * wx.x + sv * wsv.x;
            acc[c4 * 4 + 1] += xv * wx.y + sv * wsv.y;
            acc[c4 * 4 + 2] += xv * wx.z + sv * wsv.z;
            acc[c4 * 4 + 3] += xv * wx.w + sv * wsv.w;
        }
    }
    #pragma unroll
    for (int c4 = 0; c4 < 4; c4++) {
        float4 o = make_float4(fmaxf(acc[c4 * 4 + 0], 0.f), fmaxf(acc[c4 * 4 + 1], 0.f),
                               fmaxf(acc[c4 * 4 + 2], 0.f), fmaxf(acc[c4 * 4 + 3], 0.f));
        *(float4*)&H[(nb + ni) * NF + jb + c4 * 4] = o;
    }
}

// ---------------------------------------------------------------------------
// logits = H @ WL^T -> log_softmax (16 classes). 16 nodes/block, 256 threads.
// ---------------------------------------------------------------------------
__global__ __launch_bounds__(256) void logsm_kernel(const float* __restrict__ H,
                                                    const float* __restrict__ WL,
                                                    float* __restrict__ out) {
    __shared__ float Ws[16 * 65];
    __shared__ float hs[16 * 64];
    const int tid  = threadIdx.x;
    const int base = blockIdx.x * 16 * 64;

    #pragma unroll
    for (int i = 0; i < 4; i++) {
        const int idx = tid + i * 256;
        Ws[(idx >> 6) * 65 + (idx & 63)] = WL[idx];
        hs[idx] = H[base + idx];
    }
    __syncthreads();

    const int c = tid & 15, ni = tid >> 4;
    float acc = 0.f;
    #pragma unroll
    for (int f = 0; f < 64; f++)
        acc += hs[ni * 64 + f] * Ws[c * 65 + f];

    float m = acc;
    #pragma unroll
    for (int off = 8; off; off >>= 1)
        m = fmaxf(m, __shfl_xor_sync(0xffffffffu, m, off));
    float e = expf(acc - m);
    float s = e;
    #pragma unroll
    for (int off = 8; off; off >>= 1)
        s += __shfl_xor_sync(0xffffffffu, s, off);

    out[blockIdx.x * 16 * 16 + ni * 16 + c] = acc - m - logf(s);
}

// ---------------------------------------------------------------------------
extern "C" void kernel_launch(void* const* d_in, const int* in_sizes, int n_in,
                              void* d_out, int out_size) {
    const float* x   = (const float*)d_in[0];
    const float* adj = (const float*)d_in[1];
    const float* W1  = (const float*)d_in[2];
    const float* W2  = (const float*)d_in[3];
    const float* WL  = (const float*)d_in[4];
    float* out = (float*)d_out;

    void *ps, *ph1, *ph2, *pbh, *pbl;
    cudaGetSymbolAddress(&ps,  g_s);
    cudaGetSymbolAddress(&ph1, g_h1);
    cudaGetSymbolAddress(&ph2, g_h2);
    cudaGetSymbolAddress(&pbh, g_bth);
    cudaGetSymbolAddress(&pbl, g_btl);

    cudaFuncSetAttribute(gemm_bf, cudaFuncAttributeMaxDynamicSharedMemorySize, GSM);
    cudaFuncSetAttribute(layer_kernel, cudaFuncAttributeMaxDynamicSharedMemorySize, LSMEM);

    // layer 1
    bt2_kernel<<<NN / 64, 256>>>(x, (uint16_t*)pbh, (uint16_t*)pbl);
    gemm_bf<<<NN / 128, 256, GSM>>>(adj, (const uint16_t*)pbh, (const uint16_t*)pbl, (float*)ps);
    layer_kernel<<<NN / 64, 256, LSMEM>>>(x, (const float*)ps, W1, (float*)ph1);
    // layer 2
    bt2_kernel<<<NN / 64, 256>>>((const float*)ph1, (uint16_t*)pbh, (uint16_t*)pbl);
    gemm_bf<<<NN / 128, 256, GSM>>>(adj, (const uint16_t*)pbh, (const uint16_t*)pbl, (float*)ps);
    layer_kernel<<<NN / 64, 256, LSMEM>>>((const float*)ph1, (const float*)ps, W2, (float*)ph2);
    // classifier
    logsm_kernel<<<NN / 16, 256>>>((const float*)ph2, WL, out);
}

// round 4
// speedup vs baseline: 1.4182x; 1.4182x over previous
#include <cuda_runtime.h>
#include <cstdint>

#define NN 16384
#define NF 64
#define NC 16

#define NSPL 8
#define KSL  2048          // K per split
#define KT   1440          // tensor K-share
#define KF   608           // FFMA K-share
#define TIT  (KT / 32)     // 45 tensor iters
#define FIT  (KF / 32)     // 19 FFMA iters

// Scratch (no allocations allowed)
__device__ float g_part[NSPL][NN * NF];   // 32MB split-K partials
__device__ float g_h1[NN * NF];
__device__ float g_h2[NN * NF];

// ---------------------------------------------------------------------------
// helpers
// ---------------------------------------------------------------------------
__device__ __forceinline__ uint32_t f2tf(float f) {
    uint32_t u;
    asm("cvt.rna.tf32.f32 %0, %1;" : "=r"(u) : "f"(f));
    return u;
}
__device__ __forceinline__ void mma_tf32(float* c, const uint32_t* a, const uint32_t* b) {
    asm volatile(
        "mma.sync.aligned.m16n8k8.row.col.f32.tf32.tf32.f32 "
        "{%0,%1,%2,%3}, {%4,%5,%6,%7}, {%8,%9}, {%0,%1,%2,%3};"
        : "+f"(c[0]), "+f"(c[1]), "+f"(c[2]), "+f"(c[3])
        : "r"(a[0]), "r"(a[1]), "r"(a[2]), "r"(a[3]),
          "r"(b[0]), "r"(b[1]));
}
__device__ __forceinline__ void barT() { asm volatile("bar.sync 1, 256;" ::: "memory"); }
__device__ __forceinline__ void barF() { asm volatile("bar.sync 2, 256;" ::: "memory"); }

// ---------------------------------------------------------------------------
// Hybrid GEMM: P[ks] = A[rows, kslice] @ B[kslice, 64]
//   warps 0-7 : tf32 mma path over K=[k0, k0+KT)      (R1-proven structure)
//   warps 8-15: fp32 FFMA path over K=[k0+KT, k0+KSL)
// grid = 128 m-tiles * 8 k-splits = 1024, block = 512.
// ---------------------------------------------------------------------------
#define LDA 36
#define LDB 72
#define TBYTES ((2 * 128 * LDA + 2 * 32 * LDB) * 4)   // 55296 tensor stages
#define ABYTES (2 * 32 * 128 * 4)                     // 32768 FFMA A stages
#define BBYTES (2 * 32 * 68 * 4)                      // 17408 FFMA B stages
#define GSM (TBYTES + ABYTES + BBYTES)                // 105472

__global__ __launch_bounds__(512, 1) void gemm_hyb(const float* __restrict__ A,
                                                   const float* __restrict__ B,
                                                   float* __restrict__ P) {
    extern __shared__ char smraw[];
    uint32_t* Ts  = (uint32_t*)smraw;                 // tensor stages
    float*    Asf = (float*)(smraw + TBYTES);         // FFMA A stages [2][32][128]
    float*    Bsf = (float*)(smraw + TBYTES + ABYTES);// FFMA B stages [2][32][68]
    float*    Cs  = (float*)(smraw + TBYTES);         // combine buffer (reuse Asf)

    const int tidx = threadIdx.x;
    const int mtile = blockIdx.x >> 3;
    const int ks    = blockIdx.x & 7;
    const int br    = mtile * 128;
    const int k0    = ks * KSL;
    float* Pk = P + (size_t)ks * NN * NF;

    const bool tensor = (tidx < 256);

    // tensor-group per-thread constants (used again after the global barrier)
    const int tid  = tidx & 255;
    const int lane = tid & 31, warp = tid >> 5;
    const int g = lane >> 2, tq = lane & 3;
    const int wm = (warp & 3) * 32;
    const int wn = (warp >> 2) * 32;
    float tacc[2][4][4];

    if (tensor) {
        // ===================== tensor path (R1 structure) ====================
        uint32_t* As = Ts;                    // [2][128][LDA]
        uint32_t* Bs = Ts + 2 * 128 * LDA;    // [2][32][LDB]

        const int arow = tid >> 3;            // 0..31
        const int ak4  = (tid & 7) * 4;
        const int bk   = tid >> 4;            // 0..15
        const int bn4  = (tid & 15) * 4;

        float4 ra[4], rb[2];

        auto ldg = [&](int kt) {
            #pragma unroll
            for (int b = 0; b < 4; b++)
                ra[b] = *(const float4*)&A[(size_t)(br + arow + b * 32) * NN + kt + ak4];
            #pragma unroll
            for (int b = 0; b < 2; b++)
                rb[b] = *(const float4*)&B[(size_t)(kt + bk + b * 16) * NF + bn4];
        };
        auto sts = [&](int buf) {
            uint32_t* a_ = As + buf * 128 * LDA;
            uint32_t* b_ = Bs + buf * 32 * LDB;
            #pragma unroll
            for (int b = 0; b < 4; b++) {
                uint4 v = make_uint4(f2tf(ra[b].x), f2tf(ra[b].y), f2tf(ra[b].z), f2tf(ra[b].w));
                *(uint4*)&a_[(arow + b * 32) * LDA + ak4] = v;
            }
            #pragma unroll
            for (int b = 0; b < 2; b++) {
                uint4 v = make_uint4(f2tf(rb[b].x), f2tf(rb[b].y), f2tf(rb[b].z), f2tf(rb[b].w));
                *(uint4*)&b_[(bk + b * 16) * LDB + bn4] = v;
            }
        };

        #pragma unroll
        for (int im = 0; im < 2; im++)
            #pragma unroll
            for (int in_ = 0; in_ < 4; in_++)
                #pragma unroll
                for (int r = 0; r < 4; r++) tacc[im][in_][r] = 0.f;

        ldg(k0);
        sts(0);
        barT();
        ldg(k0 + 32);

        for (int it = 0; it < TIT; ++it) {
            const int cur = it & 1;
            if (it + 1 < TIT) sts(cur ^ 1);
            if (it + 2 < TIT) ldg(k0 + (it + 2) * 32);

            const uint32_t* a_ = As + cur * 128 * LDA;
            const uint32_t* b_ = Bs + cur * 32 * LDB;
            #pragma unroll
            for (int kk = 0; kk < 32; kk += 8) {
                uint32_t af[2][4], bf[4][2];
                #pragma unroll
                for (int im = 0; im < 2; im++) {
                    const int r0 = wm + im * 16;
                    af[im][0] = a_[(r0 + g    ) * LDA + kk + tq    ];
                    af[im][1] = a_[(r0 + g + 8) * LDA + kk + tq    ];
                    af[im][2] = a_[(r0 + g    ) * LDA + kk + tq + 4];
                    af[im][3] = a_[(r0 + g + 8) * LDA + kk + tq + 4];
                }
                #pragma unroll
                for (int in_ = 0; in_ < 4; in_++) {
                    bf[in_][0] = b_[(kk + tq    ) * LDB + wn + in_ * 8 + g];
                    bf[in_][1] = b_[(kk + tq + 4) * LDB + wn + in_ * 8 + g];
                }
                #pragma unroll
                for (int im = 0; im < 2; im++)
                    #pragma unroll
                    for (int in_ = 0; in_ < 4; in_++)
                        mma_tf32(tacc[im][in_], af[im], bf[in_]);
            }
            barT();
        }
    } else {
        // ===================== FFMA path =====================================
        const int t    = tidx - 256;
        const int row  = t & 127;        // A staging row
        const int half = t >> 7;         // k half (0/1)
        const int fi   = t >> 3;         // 0..31 -> output rows fi*4..+3
        const int fj   = t & 7;          // output cols fj*8..+7
        const int k0f  = k0 + KT;

        float4 fa[4], fb[2];

        auto fldg = [&](int it) {
            const int kA = k0f + it * 32 + half * 16;
            #pragma unroll
            for (int m4 = 0; m4 < 4; m4++)
                fa[m4] = *(const float4*)&A[(size_t)(br + row) * NN + kA + m4 * 4];
            #pragma unroll
            for (int j = 0; j < 2; j++) {
                const int c = t + j * 256;
                const int krow = c >> 4, nb = (c & 15) * 4;
                fb[j] = *(const float4*)&B[(size_t)(k0f + it * 32 + krow) * NF + nb];
            }
        };
        auto fsts = [&](int buf) {
            float* a_ = Asf + buf * 4096;
            float* b_ = Bsf + buf * 2176;
            #pragma unroll
            for (int m4 = 0; m4 < 4; m4++) {
                a_[(half * 16 + m4 * 4 + 0) * 128 + row] = fa[m4].x;
                a_[(half * 16 + m4 * 4 + 1) * 128 + row] = fa[m4].y;
                a_[(half * 16 + m4 * 4 + 2) * 128 + row] = fa[m4].z;
                a_[(half * 16 + m4 * 4 + 3) * 128 + row] = fa[m4].w;
            }
            #pragma unroll
            for (int j = 0; j < 2; j++) {
                const int c = t + j * 256;
                const int krow = c >> 4, nb = (c & 15) * 4;
                *(float4*)&b_[krow * 68 + nb] = fb[j];
            }
        };

        float facc[4][8];
        #pragma unroll
        for (int r = 0; r < 4; r++)
            #pragma unroll
            for (int c = 0; c < 8; c++) facc[r][c] = 0.f;

        fldg(0);
        fsts(0);
        barF();

        for (int it = 0; it < FIT; ++it) {
            const int buf = it & 1;
            if (it + 1 < FIT) fldg(it + 1);

            const float* a_ = Asf + buf * 4096;
            const float* b_ = Bsf + buf * 2176;
            #pragma unroll 8
            for (int k = 0; k < 32; k++) {
                float4 av = *(const float4*)&a_[k * 128 + fi * 4];
                float4 b0 = *(const float4*)&b_[k * 68 + fj * 8];
                float4 b1 = *(const float4*)&b_[k * 68 + fj * 8 + 4];
                const float ar[4] = {av.x, av.y, av.z, av.w};
                const float bc[8] = {b0.x, b0.y, b0.z, b0.w, b1.x, b1.y, b1.z, b1.w};
                #pragma unroll
                for (int r = 0; r < 4; r++)
                    #pragma unroll
                    for (int c = 0; c < 8; c++)
                        facc[r][c] += ar[r] * bc[c];
            }
            if (it + 1 < FIT) {
                fsts(buf ^ 1);
                barF();
            }
        }

        // publish FFMA result to Cs (reuses Asf region) after group barrier
        barF();
        #pragma unroll
        for (int r = 0; r < 4; r++) {
            *(float4*)&Cs[(fi * 4 + r) * 64 + fj * 8]     =
                make_float4(facc[r][0], facc[r][1], facc[r][2], facc[r][3]);
            *(float4*)&Cs[(fi * 4 + r) * 64 + fj * 8 + 4] =
                make_float4(facc[r][4], facc[r][5], facc[r][6], facc[r][7]);
        }
    }

    __syncthreads();   // single block-wide barrier: Cs visible to tensor group

    if (tensor) {
        #pragma unroll
        for (int t16 = 0; t16 < 2; t16++)
            #pragma unroll
            for (int nt = 0; nt < 4; nt++) {
                const int rl = wm + t16 * 16 + g;
                const int c0 = wn + nt * 8 + 2 * tq;
                float v0 = tacc[t16][nt][0] + Cs[rl * 64 + c0];
                float v1 = tacc[t16][nt][1] + Cs[rl * 64 + c0 + 1];
                float v2 = tacc[t16][nt][2] + Cs[(rl + 8) * 64 + c0];
                float v3 = tacc[t16][nt][3] + Cs[(rl + 8) * 64 + c0 + 1];
                *(float2*)&Pk[(size_t)(br + rl) * NF + c0]     = make_float2(v0, v1);
                *(float2*)&Pk[(size_t)(br + rl + 8) * NF + c0] = make_float2(v2, v3);
            }
    }
}

// ---------------------------------------------------------------------------
// H = relu([X | sum_s SP[s]] @ W), W [128][64]. 64 nodes/block, 256 threads.
// ---------------------------------------------------------------------------
#define LSMEM (128 * 64 * 4 + 2 * 64 * 68 * 4)
__global__ __launch_bounds__(256) void layer_kernel(const float* __restrict__ X,
                                                    const float* __restrict__ SP,
                                                    const float* __restrict__ W,
                                                    float* __restrict__ H) {
    extern __shared__ float lsm[];
    float* Ws = lsm;                // [128][64]
    float* xs = Ws + 128 * 64;      // [64][68]
    float* ss = xs + 64 * 68;       // [64][68]
    const int tid  = threadIdx.x;
    const size_t nb = (size_t)blockIdx.x * 64;

    #pragma unroll
    for (int j = 0; j < 8; j++)
        *(float4*)&Ws[(tid + j * 256) * 4] = *(const float4*)&W[(tid + j * 256) * 4];
    #pragma unroll
    for (int j = 0; j < 4; j++) {
        const int idx = tid + j * 256;
        const int r = idx >> 4, c = (idx & 15) * 4;
        float4 xv = *(const float4*)&X[(nb + r) * NF + c];
        float4 sv = make_float4(0.f, 0.f, 0.f, 0.f);
        #pragma unroll
        for (int s = 0; s < NSPL; s++) {
            float4 p = *(const float4*)&SP[(size_t)s * NN * NF + (nb + r) * NF + c];
            sv.x += p.x; sv.y += p.y; sv.z += p.z; sv.w += p.w;
        }
        xs[r * 68 + c] = xv.x; xs[r * 68 + c + 1] = xv.y;
        xs[r * 68 + c + 2] = xv.z; xs[r * 68 + c + 3] = xv.w;
        ss[r * 68 + c] = sv.x; ss[r * 68 + c + 1] = sv.y;
        ss[r * 68 + c + 2] = sv.z; ss[r * 68 + c + 3] = sv.w;
    }
    __syncthreads();

    const int ni = tid >> 2, jb = (tid & 3) * 16;
    float acc[16];
    #pragma unroll
    for (int c = 0; c < 16; c++) acc[c] = 0.f;

    #pragma unroll 8
    for (int f = 0; f < 64; f++) {
        const float xv = xs[ni * 68 + f];
        const float sv = ss[ni * 68 + f];
        #pragma unroll
        for (int c4 = 0; c4 < 4; c4++) {
            float4 wx  = *(const float4*)&Ws[f * 64 + jb + c4 * 4];
            float4 wsv = *(const float4*)&Ws[(64 + f) * 64 + jb + c4 * 4];
            acc[c4 * 4 + 0] += xv * wx.x + sv * wsv.x;
            acc[c4 * 4 + 1] += xv * wx.y + sv * wsv.y;
            acc[c4 * 4 + 2] += xv * wx.z + sv * wsv.z;
            acc[c4 * 4 + 3] += xv * wx.w + sv * wsv.w;
        }
    }
    #pragma unroll
    for (int c4 = 0; c4 < 4; c4++) {
        float4 o = make_float4(fmaxf(acc[c4 * 4 + 0], 0.f), fmaxf(acc[c4 * 4 + 1], 0.f),
                               fmaxf(acc[c4 * 4 + 2], 0.f), fmaxf(acc[c4 * 4 + 3], 0.f));
        *(float4*)&H[(nb + ni) * NF + jb + c4 * 4] = o;
    }
}

// ---------------------------------------------------------------------------
// logits = H @ WL^T -> log_softmax (16 classes). 16 nodes/block, 256 threads.
// ---------------------------------------------------------------------------
__global__ __launch_bounds__(256) void logsm_kernel(const float* __restrict__ H,
                                                    const float* __restrict__ WL,
                                                    float* __restrict__ out) {
    __shared__ float Ws[16 * 65];
    __shared__ float hs[16 * 64];
    const int tid  = threadIdx.x;
    const int base = blockIdx.x * 16 * 64;

    #pragma unroll
    for (int i = 0; i < 4; i++) {
        const int idx = tid + i * 256;
        Ws[(idx >> 6) * 65 + (idx & 63)] = WL[idx];
        hs[idx] = H[base + idx];
    }
    __syncthreads();

    const int c = tid & 15, ni = tid >> 4;
    float acc = 0.f;
    #pragma unroll
    for (int f = 0; f < 64; f++)
        acc += hs[ni * 64 + f] * Ws[c * 65 + f];

    float m = acc;
    #pragma unroll
    for (int off = 8; off; off >>= 1)
        m = fmaxf(m, __shfl_xor_sync(0xffffffffu, m, off));
    float e = expf(acc - m);
    float s = e;
    #pragma unroll
    for (int off = 8; off; off >>= 1)
        s += __shfl_xor_sync(0xffffffffu, s, off);

    out[blockIdx.x * 16 * 16 + ni * 16 + c] = acc - m - logf(s);
}

// ---------------------------------------------------------------------------
extern "C" void kernel_launch(void* const* d_in, const int* in_sizes, int n_in,
                              void* d_out, int out_size) {
    const float* x   = (const float*)d_in[0];
    const float* adj = (const float*)d_in[1];
    const float* W1  = (const float*)d_in[2];
    const float* W2  = (const float*)d_in[3];
    const float* WL  = (const float*)d_in[4];
    float* out = (float*)d_out;

    void *pp, *ph1, *ph2;
    cudaGetSymbolAddress(&pp,  g_part);
    cudaGetSymbolAddress(&ph1, g_h1);
    cudaGetSymbolAddress(&ph2, g_h2);

    cudaFuncSetAttribute(gemm_hyb, cudaFuncAttributeMaxDynamicSharedMemorySize, GSM);
    cudaFuncSetAttribute(layer_kernel, cudaFuncAttributeMaxDynamicSharedMemorySize, LSMEM);

    // layer 1
    gemm_hyb<<<(NN / 128) * NSPL, 512, GSM>>>(adj, x, (float*)pp);
    layer_kernel<<<NN / 64, 256, LSMEM>>>(x, (const float*)pp, W1, (float*)ph1);
    // layer 2
    gemm_hyb<<<(NN / 128) * NSPL, 512, GSM>>>(adj, (const float*)ph1, (float*)pp);
    layer_kernel<<<NN / 64, 256, LSMEM>>>((const float*)ph1, (const float*)pp, W2, (float*)ph2);
    // classifier
    logsm_kernel<<<NN / 16, 256>>>((const float*)ph2, WL, out);
}